// round 4
// baseline (speedup 1.0000x reference)
#include <cuda_runtime.h>
#include <cuda_fp16.h>
#include <cstdint>
#include <cstring>

// ---------------- problem constants ----------------
#define ZT     128          // z rows per CTA
#define NTH    256          // 8 warps
#define NITER  64           // i loop

#define FS_STRIDE 68        // fp32 elements per padded f row (bank-spread, 16B align)

// smem layout (bytes)
#define OFF_B    0                        // 2 x 8KB B tiles
#define OFF_FS   16384                    // f tile: 128 * 68 * 4 = 34816
#define SMEM_TOTAL (16384 + ZT * FS_STRIDE * 4)

// Scratch: pre-swizzled fp16 B tiles: for each i, 64(j) x 64(k) fp16 = 8KB,
// byte layout: off = j*128 + k*2, swizzled off ^= (j&7)<<4.
__device__ __align__(1024) unsigned char g_B[64 * 8192];

// ---------------- helpers ----------------
__device__ __forceinline__ uint32_t smem_u32(const void* p) {
    uint32_t a;
    asm("{ .reg .u64 t; cvta.to.shared.u64 t, %1; cvt.u32.u64 %0, t; }"
        : "=r"(a) : "l"(p));
    return a;
}

__device__ __forceinline__ uint32_t h2u(float lo, float hi) {
    __half2 h = __floats2half2_rn(lo, hi);
    uint32_t u;
    memcpy(&u, &h, 4);
    return u;
}

__device__ __forceinline__ void cpa16(uint32_t s, const void* g) {
    asm volatile("cp.async.cg.shared.global [%0], [%1], 16;" :: "r"(s), "l"(g) : "memory");
}

__device__ __forceinline__ void ldsm4t(uint32_t* r, uint32_t addr) {
    asm volatile(
        "ldmatrix.sync.aligned.m8n8.x4.trans.shared.b16 {%0,%1,%2,%3}, [%4];"
        : "=r"(r[0]), "=r"(r[1]), "=r"(r[2]), "=r"(r[3]) : "r"(addr));
}

__device__ __forceinline__ void mma16816(float* d,
                                         uint32_t a0, uint32_t a1, uint32_t a2, uint32_t a3,
                                         uint32_t b0, uint32_t b1) {
    asm volatile(
        "mma.sync.aligned.m16n8k16.row.col.f32.f16.f16.f32 "
        "{%0,%1,%2,%3}, {%4,%5,%6,%7}, {%8,%9}, {%0,%1,%2,%3};"
        : "+f"(d[0]), "+f"(d[1]), "+f"(d[2]), "+f"(d[3])
        : "r"(a0), "r"(a1), "r"(a2), "r"(a3), "r"(b0), "r"(b1));
}

// ---------------- precompute: M = sum_w w * mix, fp16, pre-swizzled ----------------
extern "C" __global__ void lts_prep(const float* __restrict__ mix,
                                    const float* __restrict__ wgt) {
    __shared__ float ws[32];
    if (threadIdx.x < 32) ws[threadIdx.x] = wgt[threadIdx.x];
    __syncthreads();

    int idx = blockIdx.x * 256 + threadIdx.x;  // = k*4096 + i*64 + j
    int j = idx & 63;
    int i = (idx >> 6) & 63;
    int k = idx >> 12;

    float s = 0.f;
#pragma unroll
    for (int w = 0; w < 32; ++w)
        s += ws[w] * __ldg(mix + (size_t)w * 262144 + idx);

    unsigned short h;
    {
        __half hh = __float2half_rn(s);
        memcpy(&h, &hh, 2);
    }
    uint32_t off = (uint32_t)j * 128 + (uint32_t)k * 2;
    off ^= ((uint32_t)(j & 7)) << 4;               // SW128-style swizzle
    *(unsigned short*)(g_B + (size_t)i * 8192 + off) = h;
}

// ---------------- main kernel ----------------
extern "C" __global__ void __launch_bounds__(NTH, 2)
lts_main(const float* __restrict__ f, float* __restrict__ out) {
    extern __shared__ __align__(1024) unsigned char smem[];
    const uint32_t sb = smem_u32(smem);
    float* fs = (float*)(smem + OFF_FS);

    const int tid  = threadIdx.x;
    const int wid  = tid >> 5;
    const int lane = tid & 31;
    const int z0   = blockIdx.x * ZT;

    // ---- cooperative load of f tile [ZT x 64] into padded smem
    {
        const float4* src = (const float4*)(f + (size_t)z0 * 64);
#pragma unroll
        for (int q = 0; q < (ZT * 16) / NTH; ++q) {
            int idx = tid + q * NTH;            // float4 index
            int row = idx >> 4;
            int c4  = idx & 15;
            float4 v = src[idx];
            *(float4*)(fs + row * FS_STRIDE + c4 * 4) = v;
        }
    }

    // ---- prefetch B_0 (8KB / 256 threads = 32B each)
    {
        uint32_t dst = sb + OFF_B + tid * 32;
        const unsigned char* src = g_B + tid * 32;
        cpa16(dst, src); cpa16(dst + 16, src + 16);
        asm volatile("cp.async.commit_group;" ::: "memory");
    }

    __syncthreads();   // f tile visible

    // ---- per-thread fragment geometry (m16n8k16)
    const int g  = lane >> 2;                 // row group 0..7
    const int c  = lane & 3;                  // col pair 0..3
    const int r0 = wid * 16 + g;              // local z row (and r0+8)
    const int r1 = r0 + 8;

    // f_j values this thread needs for its A fragments:
    // per k-step s: j = 16s + {2c, 2c+1, 2c+8, 2c+9}
    float fj0[16], fj1[16];
#pragma unroll
    for (int s = 0; s < 4; ++s) {
        float2 p0 = *(float2*)(fs + r0 * FS_STRIDE + 16 * s + 2 * c);
        float2 p1 = *(float2*)(fs + r0 * FS_STRIDE + 16 * s + 2 * c + 8);
        float2 q0 = *(float2*)(fs + r1 * FS_STRIDE + 16 * s + 2 * c);
        float2 q1 = *(float2*)(fs + r1 * FS_STRIDE + 16 * s + 2 * c + 8);
        fj0[4 * s + 0] = p0.x; fj0[4 * s + 1] = p0.y;
        fj0[4 * s + 2] = p1.x; fj0[4 * s + 3] = p1.y;
        fj1[4 * s + 0] = q0.x; fj1[4 * s + 1] = q0.y;
        fj1[4 * s + 2] = q1.x; fj1[4 * s + 3] = q1.y;
    }

    // ldmatrix address components (buffer-local), XOR applied after adds
    const uint32_t row_base = (lane & 7) + 8 * ((lane >> 3) & 1); // 0..15
    const uint32_t n0_base  = 8 * (lane >> 4);                    // 0 or 8
    const uint32_t raw      = row_base * 128 + n0_base * 2;
    const uint32_t xconst   = (row_base & 7) << 4;

    float acc[8][4];
#pragma unroll
    for (int p = 0; p < 8; ++p)
#pragma unroll
        for (int e = 0; e < 4; ++e) acc[p][e] = 0.f;

    // ---- main i loop
#pragma unroll 2
    for (int i = 0; i < NITER; ++i) {
        const uint32_t bbuf = sb + OFF_B + (uint32_t)(i & 1) * 8192;

        // B_i arrived
        asm volatile("cp.async.wait_group 0;" ::: "memory");
        __syncthreads();

        // prefetch B_{i+1} into the other buffer
        if (i + 1 < NITER) {
            uint32_t dst = sb + OFF_B + (uint32_t)((i + 1) & 1) * 8192 + tid * 32;
            const unsigned char* src = g_B + (size_t)(i + 1) * 8192 + tid * 32;
            cpa16(dst, src); cpa16(dst + 16, src + 16);
            asm volatile("cp.async.commit_group;" ::: "memory");
        }

        // form A fragments: A[z, 16s + jcols] = f[z,i] * f[z,j]
        const float a0 = fs[r0 * FS_STRIDE + i];
        const float a1 = fs[r1 * FS_STRIDE + i];
        uint32_t af[4][4];
#pragma unroll
        for (int s = 0; s < 4; ++s) {
            af[s][0] = h2u(a0 * fj0[4 * s + 0], a0 * fj0[4 * s + 1]);
            af[s][1] = h2u(a1 * fj1[4 * s + 0], a1 * fj1[4 * s + 1]);
            af[s][2] = h2u(a0 * fj0[4 * s + 2], a0 * fj0[4 * s + 3]);
            af[s][3] = h2u(a1 * fj1[4 * s + 2], a1 * fj1[4 * s + 3]);
        }

        // 4 k-steps x 8 n-tiles
#pragma unroll
        for (int s = 0; s < 4; ++s) {
#pragma unroll
            for (int p = 0; p < 4; ++p) {
                uint32_t br[4];
                uint32_t off = (raw + (uint32_t)s * 2048 + (uint32_t)p * 32) ^ xconst;
                ldsm4t(br, bbuf + off);
                mma16816(acc[2 * p + 0], af[s][0], af[s][1], af[s][2], af[s][3], br[0], br[1]);
                mma16816(acc[2 * p + 1], af[s][0], af[s][1], af[s][2], af[s][3], br[2], br[3]);
            }
        }
    }

    // ---- epilogue: write accumulators
    {
        float* o0 = out + (size_t)(z0 + r0) * 64;
        float* o1 = out + (size_t)(z0 + r1) * 64;
#pragma unroll
        for (int p = 0; p < 8; ++p) {
            int n = p * 8 + 2 * c;
            *(float2*)(o0 + n) = make_float2(acc[p][0], acc[p][1]);
            *(float2*)(o1 + n) = make_float2(acc[p][2], acc[p][3]);
        }
    }
}

// ---------------- launch ----------------
extern "C" void kernel_launch(void* const* d_in, const int* in_sizes, int n_in,
                              void* d_out, int out_size) {
    (void)n_in; (void)out_size;
    const float* f   = (const float*)d_in[0];   // [Z, 64] fp32
    const float* mix = (const float*)d_in[1];   // [32, 64, 64, 64] fp32
    const float* wgt = (const float*)d_in[2];   // [32] fp32
    float* out = (float*)d_out;                 // [Z, 64] fp32

    const int Z = in_sizes[0] / 64;

    cudaFuncSetAttribute(lts_main, cudaFuncAttributeMaxDynamicSharedMemorySize,
                         SMEM_TOTAL);

    lts_prep<<<1024, 256>>>(mix, wgt);
    lts_main<<<Z / ZT, NTH, SMEM_TOTAL>>>(f, out);
}

// round 6
// speedup vs baseline: 1.1659x; 1.1659x over previous
#include <cuda_runtime.h>
#include <cuda_fp16.h>
#include <cstdint>
#include <cstring>

// ---------------- constants ----------------
#define ZT      128          // z rows per CTA
#define NTH     256          // 8 warps
#define NCHUNK  33           // circulant-difference chunks d=0..32

#define FSTRIDE 100          // padded fp32 stride of doubled f row (96 used)

// smem layout (bytes)
#define OFF_B    0                           // 2 x 8KB B tiles
#define OFF_FS   16384                       // f tile: 128 * 100 * 4 = 51200
#define SMEM_TOTAL (16384 + ZT * FSTRIDE * 4)

// scratch
__device__ float g_M[64 * 64 * 64];                      // fp32 M[k,i,j], 1MB
__device__ __align__(1024) unsigned char g_B[NCHUNK * 8192]; // pre-swizzled fp16 chunks

// ---------------- helpers ----------------
__device__ __forceinline__ uint32_t smem_u32(const void* p) {
    uint32_t a;
    asm("{ .reg .u64 t; cvta.to.shared.u64 t, %1; cvt.u32.u64 %0, t; }"
        : "=r"(a) : "l"(p));
    return a;
}

__device__ __forceinline__ uint32_t h2u(float lo, float hi) {
    __half2 h = __floats2half2_rn(lo, hi);
    uint32_t u;
    memcpy(&u, &h, 4);
    return u;
}

__device__ __forceinline__ void cpa16(uint32_t s, const void* g) {
    asm volatile("cp.async.cg.shared.global [%0], [%1], 16;" :: "r"(s), "l"(g) : "memory");
}

__device__ __forceinline__ void ldsm4t(uint32_t* r, uint32_t addr) {
    asm volatile(
        "ldmatrix.sync.aligned.m8n8.x4.trans.shared.b16 {%0,%1,%2,%3}, [%4];"
        : "=r"(r[0]), "=r"(r[1]), "=r"(r[2]), "=r"(r[3]) : "r"(addr));
}

__device__ __forceinline__ void mma16816(float* d,
                                         uint32_t a0, uint32_t a1, uint32_t a2, uint32_t a3,
                                         uint32_t b0, uint32_t b1) {
    asm volatile(
        "mma.sync.aligned.m16n8k16.row.col.f32.f16.f16.f32 "
        "{%0,%1,%2,%3}, {%4,%5,%6,%7}, {%8,%9}, {%0,%1,%2,%3};"
        : "+f"(d[0]), "+f"(d[1]), "+f"(d[2]), "+f"(d[3])
        : "r"(a0), "r"(a1), "r"(a2), "r"(a3), "r"(b0), "r"(b1));
}

// ---------------- prep 1: M[k,i,j] = sum_w w * mix (fp32, coalesced) ----------------
extern "C" __global__ void lts_prep1(const float* __restrict__ mix,
                                     const float* __restrict__ wgt) {
    __shared__ float ws[32];
    if (threadIdx.x < 32) ws[threadIdx.x] = wgt[threadIdx.x];
    __syncthreads();

    int idx = blockIdx.x * 256 + threadIdx.x;   // k*4096 + i*64 + j
    float s = 0.f;
#pragma unroll
    for (int w = 0; w < 32; ++w)
        s += ws[w] * __ldg(mix + (size_t)w * 262144 + idx);
    g_M[idx] = s;
}

// ---------------- prep 2: fold symmetric pairs into 33 chunks, fp16 swizzled ----------------
// chunk d, col c, out k:  B = M[k,c,j2] + (d>0 ? M[k,j2,c] : 0),  j2=(c+d)&63;
// d==32 halved (each unordered pair appears at both c and c+32).
extern "C" __global__ void lts_prep2() {
    int t = blockIdx.x * 256 + threadIdx.x;     // < 33*4096
    int d = t >> 12;
    int rem = t & 4095;
    int c = rem >> 6;
    int k = rem & 63;
    int j2 = (c + d) & 63;

    float v = g_M[k * 4096 + c * 64 + j2];
    if (d > 0) v += g_M[k * 4096 + j2 * 64 + c];
    if (d == 32) v *= 0.5f;

    unsigned short h;
    {
        __half hh = __float2half_rn(v);
        memcpy(&h, &hh, 2);
    }
    uint32_t off = (uint32_t)c * 128 + (uint32_t)k * 2;
    off ^= ((uint32_t)(c & 7)) << 4;            // SW128-style swizzle
    *(unsigned short*)(g_B + (size_t)d * 8192 + off) = h;
}

// ---------------- main kernel ----------------
extern "C" __global__ void __launch_bounds__(NTH, 2)
lts_main(const float* __restrict__ f, float* __restrict__ out) {
    extern __shared__ __align__(1024) unsigned char smem[];
    const uint32_t sb = smem_u32(smem);
    float* fs = (float*)(smem + OFF_FS);

    const int tid  = threadIdx.x;
    const int wid  = tid >> 5;
    const int lane = tid & 31;
    const int z0   = blockIdx.x * ZT;

    // ---- cooperative load of f tile [ZT x 64], row-doubled to 96 cols
    {
        const float4* src = (const float4*)(f + (size_t)z0 * 64);
#pragma unroll
        for (int q = 0; q < (ZT * 16) / NTH; ++q) {
            int idx = tid + q * NTH;            // float4 index
            int row = idx >> 4;
            int c4  = idx & 15;
            float4 v = src[idx];
            *(float4*)(fs + row * FSTRIDE + c4 * 4) = v;
            if (c4 < 8)                          // duplicate first 32 cols at 64..95
                *(float4*)(fs + row * FSTRIDE + 64 + c4 * 4) = v;
        }
    }

    // ---- prefetch B chunk 0
    {
        uint32_t dst = sb + OFF_B + tid * 32;
        const unsigned char* src = g_B + tid * 32;
        cpa16(dst, src); cpa16(dst + 16, src + 16);
        asm volatile("cp.async.commit_group;" ::: "memory");
    }

    __syncthreads();

    // ---- per-thread fragment geometry (m16n8k16)
    const int g  = lane >> 2;                 // row group 0..7
    const int c  = lane & 3;                  // col pair 0..3
    const int r0 = wid * 16 + g;
    const int r1 = r0 + 8;

    // f_c values this thread's A-fragment columns use (fixed across chunks)
    float fj0[16], fj1[16];
#pragma unroll
    for (int s = 0; s < 4; ++s) {
        float2 p0 = *(float2*)(fs + r0 * FSTRIDE + 16 * s + 2 * c);
        float2 p1 = *(float2*)(fs + r0 * FSTRIDE + 16 * s + 2 * c + 8);
        float2 q0 = *(float2*)(fs + r1 * FSTRIDE + 16 * s + 2 * c);
        float2 q1 = *(float2*)(fs + r1 * FSTRIDE + 16 * s + 2 * c + 8);
        fj0[4 * s + 0] = p0.x; fj0[4 * s + 1] = p0.y;
        fj0[4 * s + 2] = p1.x; fj0[4 * s + 3] = p1.y;
        fj1[4 * s + 0] = q0.x; fj1[4 * s + 1] = q0.y;
        fj1[4 * s + 2] = q1.x; fj1[4 * s + 3] = q1.y;
    }

    // ldmatrix address components (buffer-local)
    const uint32_t row_base = (lane & 7) + 8 * ((lane >> 3) & 1);
    const uint32_t n0_base  = 8 * (lane >> 4);
    const uint32_t raw      = row_base * 128 + n0_base * 2;
    const uint32_t xconst   = (row_base & 7) << 4;

    float acc[8][4];
#pragma unroll
    for (int p = 0; p < 8; ++p)
#pragma unroll
        for (int e = 0; e < 4; ++e) acc[p][e] = 0.f;

    // ---- main chunk loop d = 0..32
#pragma unroll 2
    for (int d = 0; d < NCHUNK; ++d) {
        const uint32_t bbuf = sb + OFF_B + (uint32_t)(d & 1) * 8192;

        asm volatile("cp.async.wait_group 0;" ::: "memory");
        __syncthreads();

        if (d + 1 < NCHUNK) {
            uint32_t dst = sb + OFF_B + (uint32_t)((d + 1) & 1) * 8192 + tid * 32;
            const unsigned char* src = g_B + (size_t)(d + 1) * 8192 + tid * 32;
            cpa16(dst, src); cpa16(dst + 16, src + 16);
            asm volatile("cp.async.commit_group;" ::: "memory");
        }

        // A fragments: A[z, col c] = f[z,c] * f[z, c+d]
        // (doubled row -> no wrap; scalar loads: base has odd-d offset, only 4B aligned)
        const float* pr0 = fs + r0 * FSTRIDE + d + 2 * c;
        const float* pr1 = fs + r1 * FSTRIDE + d + 2 * c;
        uint32_t af[4][4];
#pragma unroll
        for (int s = 0; s < 4; ++s) {
            af[s][0] = h2u(fj0[4 * s + 0] * pr0[16 * s],     fj0[4 * s + 1] * pr0[16 * s + 1]);
            af[s][1] = h2u(fj1[4 * s + 0] * pr1[16 * s],     fj1[4 * s + 1] * pr1[16 * s + 1]);
            af[s][2] = h2u(fj0[4 * s + 2] * pr0[16 * s + 8], fj0[4 * s + 3] * pr0[16 * s + 9]);
            af[s][3] = h2u(fj1[4 * s + 2] * pr1[16 * s + 8], fj1[4 * s + 3] * pr1[16 * s + 9]);
        }

        // 4 k-steps x 8 n-tiles
#pragma unroll
        for (int s = 0; s < 4; ++s) {
#pragma unroll
            for (int p = 0; p < 4; ++p) {
                uint32_t br[4];
                uint32_t off = (raw + (uint32_t)s * 2048 + (uint32_t)p * 32) ^ xconst;
                ldsm4t(br, bbuf + off);
                mma16816(acc[2 * p + 0], af[s][0], af[s][1], af[s][2], af[s][3], br[0], br[1]);
                mma16816(acc[2 * p + 1], af[s][0], af[s][1], af[s][2], af[s][3], br[2], br[3]);
            }
        }
    }

    // ---- epilogue
    {
        float* o0 = out + (size_t)(z0 + r0) * 64;
        float* o1 = out + (size_t)(z0 + r1) * 64;
#pragma unroll
        for (int p = 0; p < 8; ++p) {
            int n = p * 8 + 2 * c;
            *(float2*)(o0 + n) = make_float2(acc[p][0], acc[p][1]);
            *(float2*)(o1 + n) = make_float2(acc[p][2], acc[p][3]);
        }
    }
}

// ---------------- launch ----------------
extern "C" void kernel_launch(void* const* d_in, const int* in_sizes, int n_in,
                              void* d_out, int out_size) {
    (void)n_in; (void)out_size;
    const float* f   = (const float*)d_in[0];   // [Z, 64] fp32
    const float* mix = (const float*)d_in[1];   // [32, 64, 64, 64] fp32
    const float* wgt = (const float*)d_in[2];   // [32] fp32
    float* out = (float*)d_out;                 // [Z, 64] fp32

    const int Z = in_sizes[0] / 64;

    cudaFuncSetAttribute(lts_main, cudaFuncAttributeMaxDynamicSharedMemorySize,
                         SMEM_TOTAL);

    lts_prep1<<<1024, 256>>>(mix, wgt);
    lts_prep2<<<(NCHUNK * 4096) / 256, 256>>>();
    lts_main<<<Z / ZT, NTH, SMEM_TOTAL>>>(f, out);
}

// round 7
// speedup vs baseline: 1.5249x; 1.3079x over previous
#include <cuda_runtime.h>
#include <cuda_fp16.h>
#include <cstdint>
#include <cstring>

// ---------------- constants ----------------
#define ZT      128          // z rows per CTA
#define NTH     256          // 8 warps
#define NCHUNK  33           // circulant-difference chunks d=0..32

#define FH_STRIDE 208        // bytes per fp16 f row (104 halves, 96 used)

// smem layout (bytes)
#define OFF_B    0                            // 2 x 8KB B tiles
#define OFF_F0   16384                        // fp16 f tile (row-doubled)
#define OFF_F1   (16384 + 128 * FH_STRIDE)    // fp16 f tile shifted by one col
#define SMEM_TOTAL (OFF_F1 + 128 * FH_STRIDE) // 69632

// scratch
__device__ float g_M[64 * 64 * 64];                          // fp32 M[k,i,j], 1MB
__device__ __align__(1024) unsigned char g_B[NCHUNK * 8192]; // pre-swizzled fp16 chunks

// ---------------- helpers ----------------
__device__ __forceinline__ uint32_t smem_u32(const void* p) {
    uint32_t a;
    asm("{ .reg .u64 t; cvta.to.shared.u64 t, %1; cvt.u32.u64 %0, t; }"
        : "=r"(a) : "l"(p));
    return a;
}

__device__ __forceinline__ uint32_t h2u(float lo, float hi) {
    __half2 h = __floats2half2_rn(lo, hi);
    uint32_t u;
    memcpy(&u, &h, 4);
    return u;
}

__device__ __forceinline__ uint32_t mulh2(uint32_t a, uint32_t b) {
    uint32_t d;
    asm("mul.rn.f16x2 %0, %1, %2;" : "=r"(d) : "r"(a), "r"(b));
    return d;
}

__device__ __forceinline__ void cpa16(uint32_t s, const void* g) {
    asm volatile("cp.async.cg.shared.global [%0], [%1], 16;" :: "r"(s), "l"(g) : "memory");
}

__device__ __forceinline__ void ldsm4t(uint32_t* r, uint32_t addr) {
    asm volatile(
        "ldmatrix.sync.aligned.m8n8.x4.trans.shared.b16 {%0,%1,%2,%3}, [%4];"
        : "=r"(r[0]), "=r"(r[1]), "=r"(r[2]), "=r"(r[3]) : "r"(addr));
}

__device__ __forceinline__ void mma16816(float* d,
                                         uint32_t a0, uint32_t a1, uint32_t a2, uint32_t a3,
                                         uint32_t b0, uint32_t b1) {
    asm volatile(
        "mma.sync.aligned.m16n8k16.row.col.f32.f16.f16.f32 "
        "{%0,%1,%2,%3}, {%4,%5,%6,%7}, {%8,%9}, {%0,%1,%2,%3};"
        : "+f"(d[0]), "+f"(d[1]), "+f"(d[2]), "+f"(d[3])
        : "r"(a0), "r"(a1), "r"(a2), "r"(a3), "r"(b0), "r"(b1));
}

// ---------------- prep 1: M[k,i,j] = sum_w w * mix (fp32, float4/thread) ----------------
extern "C" __global__ void lts_prep1(const float* __restrict__ mix,
                                     const float* __restrict__ wgt) {
    __shared__ float ws[32];
    if (threadIdx.x < 32) ws[threadIdx.x] = wgt[threadIdx.x];
    __syncthreads();

    size_t idx = ((size_t)blockIdx.x * 256 + threadIdx.x) * 4;
    float4 s = make_float4(0.f, 0.f, 0.f, 0.f);
#pragma unroll
    for (int w = 0; w < 32; ++w) {
        float4 m = __ldg((const float4*)(mix + (size_t)w * 262144 + idx));
        float c = ws[w];
        s.x += c * m.x; s.y += c * m.y; s.z += c * m.z; s.w += c * m.w;
    }
    *(float4*)(g_M + idx) = s;
}

// ---------------- prep 2: fold symmetric pairs into 33 chunks, fp16 swizzled ----------------
extern "C" __global__ void lts_prep2() {
    int t = blockIdx.x * 256 + threadIdx.x;     // < 33*4096
    int d = t >> 12;
    int rem = t & 4095;
    int c = rem >> 6;
    int k = rem & 63;
    int j2 = (c + d) & 63;

    float v = g_M[k * 4096 + c * 64 + j2];
    if (d > 0) v += g_M[k * 4096 + j2 * 64 + c];
    if (d == 32) v *= 0.5f;

    unsigned short h;
    {
        __half hh = __float2half_rn(v);
        memcpy(&h, &hh, 2);
    }
    uint32_t off = (uint32_t)c * 128 + (uint32_t)k * 2;
    off ^= ((uint32_t)(c & 7)) << 4;            // SW128-style swizzle
    *(unsigned short*)(g_B + (size_t)d * 8192 + off) = h;
}

// ---------------- main kernel ----------------
extern "C" __global__ void __launch_bounds__(NTH, 2)
lts_main(const float* __restrict__ f, float* __restrict__ out) {
    extern __shared__ __align__(1024) unsigned char smem[];
    const uint32_t sb = smem_u32(smem);

    const int tid  = threadIdx.x;
    const int wid  = tid >> 5;
    const int lane = tid & 31;
    const int z0   = blockIdx.x * ZT;

    // ---- prefetch B chunk 0 early
    {
        uint32_t dst = sb + OFF_B + tid * 32;
        const unsigned char* src = g_B + tid * 32;
        cpa16(dst, src); cpa16(dst + 16, src + 16);
        asm volatile("cp.async.commit_group;" ::: "memory");
    }

    // ---- fill F0: fp16 f tile [128 x 96] (cols 64..95 duplicate 0..31), pad zero
    {
        const float4* src = (const float4*)(f + (size_t)z0 * 64);
#pragma unroll
        for (int q = 0; q < (ZT * 16) / NTH; ++q) {
            int idx = tid + q * NTH;            // float4 index
            int row = idx >> 4;
            int c4  = idx & 15;
            float4 v = src[idx];
            uint32_t w0 = h2u(v.x, v.y), w1 = h2u(v.z, v.w);
            uint32_t* p = (uint32_t*)(smem + OFF_F0 + row * FH_STRIDE + c4 * 8);
            p[0] = w0; p[1] = w1;
            if (c4 < 8) {
                uint32_t* pd = (uint32_t*)(smem + OFF_F0 + row * FH_STRIDE + 128 + c4 * 8);
                pd[0] = w0; pd[1] = w1;
            }
        }
        // zero pad words 48..51 of each row
#pragma unroll
        for (int q = 0; q < (ZT * 4) / NTH; ++q) {
            int idx = tid + q * NTH;
            int row = idx >> 2;
            int w   = idx & 3;
            *(uint32_t*)(smem + OFF_F0 + row * FH_STRIDE + 192 + w * 4) = 0;
        }
    }
    __syncthreads();

    // ---- build F1 (shifted by one half) via funnel shift of F0 words
    {
#pragma unroll
        for (int q = 0; q < (ZT * 48) / NTH; ++q) {
            int idx = tid + q * NTH;
            int row = idx / 48;
            int w   = idx - row * 48;
            const uint32_t* pr = (const uint32_t*)(smem + OFF_F0 + row * FH_STRIDE + w * 4);
            uint32_t a = pr[0], b = pr[1];
            *(uint32_t*)(smem + OFF_F1 + row * FH_STRIDE + w * 4) =
                __funnelshift_r(a, b, 16);
        }
    }

    // ---- per-thread fragment geometry (m16n8k16)
    const int g  = lane >> 2;                 // row group 0..7
    const int c  = lane & 3;                  // col pair 0..3
    const int r0 = wid * 16 + g;
    const int r1 = r0 + 8;

    // fixed factors as half2: cols (16s+2c, +1) and (16s+2c+8, +9) for r0/r1
    uint32_t fj0a[4], fj0b[4], fj1a[4], fj1b[4];
#pragma unroll
    for (int s = 0; s < 4; ++s) {
        const unsigned char* b0 = smem + OFF_F0 + r0 * FH_STRIDE + (8 * s + c) * 4;
        const unsigned char* b1 = smem + OFF_F0 + r1 * FH_STRIDE + (8 * s + c) * 4;
        fj0a[s] = *(const uint32_t*)(b0);
        fj0b[s] = *(const uint32_t*)(b0 + 16);
        fj1a[s] = *(const uint32_t*)(b1);
        fj1b[s] = *(const uint32_t*)(b1 + 16);
    }
    __syncthreads();   // F1 visible

    // ldmatrix address components (buffer-local)
    const uint32_t row_base = (lane & 7) + 8 * ((lane >> 3) & 1);
    const uint32_t n0_base  = 8 * (lane >> 4);
    const uint32_t raw      = row_base * 128 + n0_base * 2;
    const uint32_t xconst   = (row_base & 7) << 4;

    float acc[8][4];
#pragma unroll
    for (int p = 0; p < 8; ++p)
#pragma unroll
        for (int e = 0; e < 4; ++e) acc[p][e] = 0.f;

    // ---- main chunk loop d = 0..32
#pragma unroll 2
    for (int d = 0; d < NCHUNK; ++d) {
        const uint32_t bbuf = sb + OFF_B + (uint32_t)(d & 1) * 8192;

        asm volatile("cp.async.wait_group 0;" ::: "memory");
        __syncthreads();

        if (d + 1 < NCHUNK) {
            uint32_t dst = sb + OFF_B + (uint32_t)((d + 1) & 1) * 8192 + tid * 32;
            const unsigned char* src = g_B + (size_t)(d + 1) * 8192 + tid * 32;
            cpa16(dst, src); cpa16(dst + 16, src + 16);
            asm volatile("cp.async.commit_group;" ::: "memory");
        }

        // A fragments: af = h(f[col]) * h(f[col+d]), all aligned half2 LDS
        const int off_tile = (d & 1) ? (OFF_F1 + (d - 1) * 2) : (OFF_F0 + d * 2);
        const unsigned char* u0p = smem + off_tile + r0 * FH_STRIDE + c * 4;
        const unsigned char* u1p = smem + off_tile + r1 * FH_STRIDE + c * 4;
        uint32_t af[4][4];
#pragma unroll
        for (int s = 0; s < 4; ++s) {
            uint32_t u00 = *(const uint32_t*)(u0p + s * 32);
            uint32_t u01 = *(const uint32_t*)(u0p + s * 32 + 16);
            uint32_t u10 = *(const uint32_t*)(u1p + s * 32);
            uint32_t u11 = *(const uint32_t*)(u1p + s * 32 + 16);
            af[s][0] = mulh2(fj0a[s], u00);
            af[s][1] = mulh2(fj1a[s], u10);
            af[s][2] = mulh2(fj0b[s], u01);
            af[s][3] = mulh2(fj1b[s], u11);
        }

        // 4 k-steps x 8 n-tiles
#pragma unroll
        for (int s = 0; s < 4; ++s) {
#pragma unroll
            for (int p = 0; p < 4; ++p) {
                uint32_t br[4];
                uint32_t off = (raw + (uint32_t)s * 2048 + (uint32_t)p * 32) ^ xconst;
                ldsm4t(br, bbuf + off);
                mma16816(acc[2 * p + 0], af[s][0], af[s][1], af[s][2], af[s][3], br[0], br[1]);
                mma16816(acc[2 * p + 1], af[s][0], af[s][1], af[s][2], af[s][3], br[2], br[3]);
            }
        }
    }

    // ---- epilogue
    {
        float* o0 = out + (size_t)(z0 + r0) * 64;
        float* o1 = out + (size_t)(z0 + r1) * 64;
#pragma unroll
        for (int p = 0; p < 8; ++p) {
            int n = p * 8 + 2 * c;
            *(float2*)(o0 + n) = make_float2(acc[p][0], acc[p][1]);
            *(float2*)(o1 + n) = make_float2(acc[p][2], acc[p][3]);
        }
    }
}

// ---------------- launch ----------------
extern "C" void kernel_launch(void* const* d_in, const int* in_sizes, int n_in,
                              void* d_out, int out_size) {
    (void)n_in; (void)out_size;
    const float* f   = (const float*)d_in[0];   // [Z, 64] fp32
    const float* mix = (const float*)d_in[1];   // [32, 64, 64, 64] fp32
    const float* wgt = (const float*)d_in[2];   // [32] fp32
    float* out = (float*)d_out;                 // [Z, 64] fp32

    const int Z = in_sizes[0] / 64;

    cudaFuncSetAttribute(lts_main, cudaFuncAttributeMaxDynamicSharedMemorySize,
                         SMEM_TOTAL);

    lts_prep1<<<256, 256>>>(mix, wgt);
    lts_prep2<<<(NCHUNK * 4096) / 256, 256>>>();
    lts_main<<<Z / ZT, NTH, SMEM_TOTAL>>>(f, out);
}